// round 9
// baseline (speedup 1.0000x reference)
#include <cuda_runtime.h>
#include <cuda_fp16.h>

#define NN 100000
#define EE 3200000
#define GG 1024

// ---- scratch (allocation-free: __device__ globals; zero-init at load,
//      every kernel restores what it consumes so graph replays are identical) ----
__device__ int    d_is64;                  // published by k_prep block 0
__device__ __align__(16) float  d_deg[NN];   // RED target; zeroed by k_node0 after use
__device__ float  d_dinv[NN];
__device__ __align__(16) int2   d_rc[EE];    // int64 path only
__device__ __align__(16) __half d_p[NN * 8];     // layer-1 message (5 halves in 16B)
__device__ __align__(16) __half d_s[NN * 8];     // layer-1 aggregate
__device__ __align__(16) __half d_g2[NN * 8];    // layer-2 message (8 halves in 16B)
__device__ __align__(16) __half d_acc2[NN * 8];  // layer-2 aggregate
__device__ float  d_zsum[GG];              // pooled z; zeroed by k_final after use
__device__ float  d_cntf[GG];              // pooled count; zeroed by k_final after use

__device__ __forceinline__ unsigned h2u(__half2 h) { return *reinterpret_cast<unsigned*>(&h); }
__device__ __forceinline__ __half2 u2h(unsigned u) { return *reinterpret_cast<__half2*>(&u); }

// detect int64 vs int32 indices: odd int32 words of an int64 array of values < 1e5
// are all zero; for int32 data they are random row indices (P(all zero) ~ 1e-80).
__device__ __forceinline__ int detect64(const int* ei32) {
    int all0 = 1;
#pragma unroll
    for (int k = 0; k < 16; k++)
        if (ei32[2 * k + 1] != 0) all0 = 0;
    return all0;
}

// prep: degree histogram (+ int2 conversion on int64 input); publishes d_is64
__global__ void __launch_bounds__(256) k_prep(const void* __restrict__ ei, int E) {
    __shared__ int sm_is64;
    if (threadIdx.x == 0) {
        int v = detect64((const int*)ei);
        sm_is64 = v;
        if (blockIdx.x == 0) d_is64 = v;
    }
    __syncthreads();
    int e = blockIdx.x * blockDim.x + threadIdx.x;
    if (e >= E) return;
    if (sm_is64) {
        const long long* p = (const long long*)ei;
        int r = (int)p[e];
        int c = (int)p[E + e];
        d_rc[e] = make_int2(r, c);
        atomicAdd(&d_deg[c], 1.0f);
    } else {
        const int* p = (const int*)ei;
        atomicAdd(&d_deg[p[E + e]], 1.0f);
    }
}

// node prologue: dinv = rsqrt(1+indeg); restore d_deg to 0; pack fp16 message; s = p
__global__ void k_node0(const float* __restrict__ x) {
    int i = blockIdx.x * blockDim.x + threadIdx.x;
    if (i >= NN) return;
    float dinv = rsqrtf(1.0f + d_deg[i]);
    d_deg[i] = 0.0f;                      // restore for next replay
    d_dinv[i] = dinv;
    float4 xi = reinterpret_cast<const float4*>(x)[i];
    uint4 pk;
    pk.x = h2u(__floats2half2_rn(dinv * xi.x, dinv * xi.y));
    pk.y = h2u(__floats2half2_rn(dinv * xi.z, dinv * xi.w));
    pk.z = h2u(__floats2half2_rn(dinv, 0.0f));
    pk.w = 0u;
    reinterpret_cast<uint4*>(&d_p[i * 8])[0] = pk;
    reinterpret_cast<uint4*>(&d_s[i * 8])[0] = pk;
}

__device__ __forceinline__ void load_rc(const void* ei, int E, int e, int& r, int& c) {
    if (d_is64) {
        int2 rc = d_rc[e];
        r = rc.x; c = rc.y;
    } else {
        const int* p = (const int*)ei;
        r = __ldg(&p[e]);
        c = __ldg(&p[E + e]);
    }
}

// edge scatter layer 1: s[col] += p[row]   (16B gather + one red.v4.f16x2)
__global__ void __launch_bounds__(256) k_edge1(const void* __restrict__ ei, int E) {
    int e = blockIdx.x * blockDim.x + threadIdx.x;
    if (e >= E) return;
    int r, c;
    load_rc(ei, E, e, r, c);
    uint4 v = reinterpret_cast<const uint4*>(&d_p[r * 8])[0];
    asm volatile("red.global.add.noftz.v4.f16x2 [%0], {%1,%2,%3,%4};"
                 :: "l"(&d_s[c * 8]), "r"(v.x), "r"(v.y), "r"(v.z), "r"(v.w)
                 : "memory");
}

// node mid: unpack fp16 aggregate, reconstruct 7-dim, W1+b1, tanh, g2=(h1@W2^T)*dinv
__global__ void k_node1(const float* __restrict__ W_emb,
                        const float* __restrict__ b_emb,
                        const float* __restrict__ W1,
                        const float* __restrict__ b1,
                        const float* __restrict__ W2) {
    int i = blockIdx.x * blockDim.x + threadIdx.x;
    if (i >= NN) return;
    float dinv = d_dinv[i];
    uint4 sv = reinterpret_cast<const uint4*>(&d_s[i * 8])[0];
    float2 f0 = __half22float2(u2h(sv.x));   // S.x0, S.x
    float2 f1 = __half22float2(u2h(sv.y));   // S.y, S.z
    float2 f2 = __half22float2(u2h(sv.z));   // S1, -
    float a[7];
#pragma unroll
    for (int j = 0; j < 4; j++)
        a[j] = dinv * fmaf(W_emb[j], f0.x, b_emb[j] * f2.x);
    a[4] = dinv * f0.y;
    a[5] = dinv * f1.x;
    a[6] = dinv * f1.y;
    float h[16];
#pragma unroll
    for (int k = 0; k < 16; k++) {
        float s = b1[k];
#pragma unroll
        for (int j = 0; j < 7; j++) s = fmaf(W1[k * 7 + j], a[j], s);
        h[k] = tanhf(s);
    }
    float g[8];
#pragma unroll
    for (int m = 0; m < 8; m++) {
        float s = 0.0f;
#pragma unroll
        for (int k = 0; k < 16; k++) s = fmaf(W2[m * 16 + k], h[k], s);
        g[m] = s * dinv;
    }
    uint4 pk;
    pk.x = h2u(__floats2half2_rn(g[0], g[1]));
    pk.y = h2u(__floats2half2_rn(g[2], g[3]));
    pk.z = h2u(__floats2half2_rn(g[4], g[5]));
    pk.w = h2u(__floats2half2_rn(g[6], g[7]));
    reinterpret_cast<uint4*>(&d_g2[i * 8])[0] = pk;
    reinterpret_cast<uint4*>(&d_acc2[i * 8])[0] = pk;
}

// edge scatter layer 2: acc2[col] += g2[row]   (16B gather + one red.v4.f16x2)
__global__ void __launch_bounds__(256) k_edge2(const void* __restrict__ ei, int E) {
    int e = blockIdx.x * blockDim.x + threadIdx.x;
    if (e >= E) return;
    int r, c;
    load_rc(ei, E, e, r, c);
    uint4 v = reinterpret_cast<const uint4*>(&d_g2[r * 8])[0];
    asm volatile("red.global.add.noftz.v4.f16x2 [%0], {%1,%2,%3,%4};"
                 :: "l"(&d_acc2[c * 8]), "r"(v.x), "r"(v.y), "r"(v.z), "r"(v.w)
                 : "memory");
}

// node epilogue: h2 = tanh(dinv*acc2 + b2); z = h2 . W3; pool z and count (2 atomics)
__global__ void k_node2(const void* __restrict__ batch,
                        const float* __restrict__ b2,
                        const float* __restrict__ W3) {
    int i = blockIdx.x * blockDim.x + threadIdx.x;
    if (i >= NN) return;
    float dinv = d_dinv[i];
    int b = d_is64 ? (int)((const long long*)batch)[i] : ((const int*)batch)[i];
    uint4 av = reinterpret_cast<const uint4*>(&d_acc2[i * 8])[0];
    float2 a0 = __half22float2(u2h(av.x));
    float2 a1 = __half22float2(u2h(av.y));
    float2 a2 = __half22float2(u2h(av.z));
    float2 a3 = __half22float2(u2h(av.w));
    float v[8] = {a0.x, a0.y, a1.x, a1.y, a2.x, a2.y, a3.x, a3.y};
    float z = 0.0f;
#pragma unroll
    for (int k = 0; k < 8; k++)
        z = fmaf(tanhf(fmaf(dinv, v[k], b2[k])), W3[k], z);
    atomicAdd(&d_zsum[b], z);
    atomicAdd(&d_cntf[b], 1.0f);
}

// final: out[g] = zsum/max(cnt,1) + b3; restore pools to zero
__global__ void k_final(const float* __restrict__ b3, float* __restrict__ out) {
    int g = blockIdx.x * blockDim.x + threadIdx.x;
    if (g >= GG) return;
    float c = fmaxf(d_cntf[g], 1.0f);
    out[g] = d_zsum[g] / c + b3[0];
    d_zsum[g] = 0.0f;                     // restore for next replay
    d_cntf[g] = 0.0f;
}

extern "C" void kernel_launch(void* const* d_in, const int* in_sizes, int n_in,
                              void* d_out, int out_size) {
    const float* x     = (const float*)d_in[0];
    const void*  ei    = d_in[1];
    const void*  batch = d_in[2];
    const float* W_emb = (const float*)d_in[3];
    const float* b_emb = (const float*)d_in[4];
    const float* W1    = (const float*)d_in[5];
    const float* b1    = (const float*)d_in[6];
    const float* W2    = (const float*)d_in[7];
    const float* b2    = (const float*)d_in[8];
    const float* W3    = (const float*)d_in[9];
    const float* b3    = (const float*)d_in[10];
    float* out = (float*)d_out;

    int E = in_sizes[1] / 2;
    if (E > EE) E = EE;

    int nb = (NN + 255) / 256;
    int eb = (E + 255) / 256;

    k_prep<<<eb, 256>>>(ei, E);
    k_node0<<<nb, 256>>>(x);
    k_edge1<<<eb, 256>>>(ei, E);
    k_node1<<<nb, 256>>>(W_emb, b_emb, W1, b1, W2);
    k_edge2<<<eb, 256>>>(ei, E);
    k_node2<<<nb, 256>>>(batch, b2, W3);
    k_final<<<(GG + 255) / 256, 256>>>(b3, out);
}

// round 10
// speedup vs baseline: 1.4553x; 1.4553x over previous
#include <cuda_runtime.h>
#include <cuda_fp16.h>

#define NN 100000
#define EE 3200000
#define GG 1024

// ---- scratch (allocation-free: __device__ globals) ----
__device__ int    d_is64;                 // 1 if index inputs are int64
__device__ __align__(16) float  d_deg[NN];
__device__ float  d_dinv[NN];
__device__ __align__(16) int2   d_rc[EE];          // int64 path only
__device__ __align__(16) __half d_p[NN * 8];       // layer-1 message (5 halves in 16B)
__device__ __align__(16) __half d_s[NN * 8];       // layer-1 aggregate (fp16 atomics)
__device__ __align__(16) __half d_g2[NN * 8];      // layer-2 message (8 halves in 16B)
__device__ __align__(16) __half d_acc2[NN * 8];    // layer-2 aggregate (fp16 atomics)
__device__ float  d_zsum[GG];
__device__ float  d_cntf[GG];

__device__ __forceinline__ unsigned h2u(__half2 h) { return *reinterpret_cast<unsigned*>(&h); }
__device__ __forceinline__ __half2 u2h(unsigned u) { return *reinterpret_cast<__half2*>(&u); }
__device__ __forceinline__ float tanh_fast(float x) {
    float y;
    asm("tanh.approx.f32 %0, %1;" : "=f"(y) : "f"(x));
    return y;
}

// init: deg=1 (self loop), pools=0, dtype detect (int64 idx < 1e5 -> high words all 0)
__global__ void k_init(const int* __restrict__ ei32) {
    int i = blockIdx.x * blockDim.x + threadIdx.x;
    if (i < NN) d_deg[i] = 1.0f;
    if (i < GG) { d_zsum[i] = 0.0f; d_cntf[i] = 0.0f; }
    if (i == 0) {
        int all0 = 1;
        for (int k = 0; k < 64; k++)
            if (ei32[2 * k + 1] != 0) { all0 = 0; break; }
        d_is64 = all0;
    }
}

// prep: degree histogram; on int64 input also write compact int2 for the hot passes
__global__ void __launch_bounds__(256) k_prep(const void* __restrict__ ei, int E) {
    int e = blockIdx.x * blockDim.x + threadIdx.x;
    if (e >= E) return;
    if (d_is64) {
        const long long* p = (const long long*)ei;
        int r = (int)p[e];
        int c = (int)p[E + e];
        d_rc[e] = make_int2(r, c);
        atomicAdd(&d_deg[c], 1.0f);
    } else {
        const int* p = (const int*)ei;
        atomicAdd(&d_deg[p[E + e]], 1.0f);
    }
}

// node prologue: dinv; p = pack16(dinv*x0, dinv*x, dinv*y, dinv*z, dinv, 0,0,0); s = p
__global__ void k_node0(const float* __restrict__ x) {
    int i = blockIdx.x * blockDim.x + threadIdx.x;
    if (i >= NN) return;
    float dinv = rsqrtf(d_deg[i]);
    d_dinv[i] = dinv;
    float4 xi = reinterpret_cast<const float4*>(x)[i];
    uint4 pk;
    pk.x = h2u(__floats2half2_rn(dinv * xi.x, dinv * xi.y));
    pk.y = h2u(__floats2half2_rn(dinv * xi.z, dinv * xi.w));
    pk.z = h2u(__floats2half2_rn(dinv, 0.0f));
    pk.w = 0u;
    reinterpret_cast<uint4*>(&d_p[i * 8])[0] = pk;
    reinterpret_cast<uint4*>(&d_s[i * 8])[0] = pk;
}

__device__ __forceinline__ void load_rc(const void* ei, int E, int e, int& r, int& c) {
    if (d_is64) {
        int2 rc = d_rc[e];
        r = rc.x; c = rc.y;
    } else {
        const int* p = (const int*)ei;
        r = __ldg(&p[e]);
        c = __ldg(&p[E + e]);
    }
}

// edge scatter layer 1: s[col] += p[row]   (16B gather + one red.v4.f16x2)
__global__ void __launch_bounds__(256) k_edge1(const void* __restrict__ ei, int E) {
    int e = blockIdx.x * blockDim.x + threadIdx.x;
    if (e >= E) return;
    int r, c;
    load_rc(ei, E, e, r, c);
    uint4 v = reinterpret_cast<const uint4*>(&d_p[r * 8])[0];
    asm volatile("red.global.add.noftz.v4.f16x2 [%0], {%1,%2,%3,%4};"
                 :: "l"(&d_s[c * 8]), "r"(v.x), "r"(v.y), "r"(v.z), "r"(v.w)
                 : "memory");
}

// node mid: unpack fp16 aggregate, reconstruct 7-dim, W1+b1, tanh, g2=(h1@W2^T)*dinv
__global__ void k_node1(const float* __restrict__ W_emb,
                        const float* __restrict__ b_emb,
                        const float* __restrict__ W1,
                        const float* __restrict__ b1,
                        const float* __restrict__ W2) {
    int i = blockIdx.x * blockDim.x + threadIdx.x;
    if (i >= NN) return;
    float dinv = d_dinv[i];
    uint4 sv = reinterpret_cast<const uint4*>(&d_s[i * 8])[0];
    float2 f0 = __half22float2(u2h(sv.x));   // S.x0, S.x
    float2 f1 = __half22float2(u2h(sv.y));   // S.y, S.z
    float2 f2 = __half22float2(u2h(sv.z));   // S1, -
    float a[7];
#pragma unroll
    for (int j = 0; j < 4; j++)
        a[j] = dinv * fmaf(W_emb[j], f0.x, b_emb[j] * f2.x);
    a[4] = dinv * f0.y;
    a[5] = dinv * f1.x;
    a[6] = dinv * f1.y;
    float h[16];
#pragma unroll
    for (int k = 0; k < 16; k++) {
        float s = b1[k];
#pragma unroll
        for (int j = 0; j < 7; j++) s = fmaf(W1[k * 7 + j], a[j], s);
        h[k] = tanh_fast(s);
    }
    float g[8];
#pragma unroll
    for (int m = 0; m < 8; m++) {
        float s = 0.0f;
#pragma unroll
        for (int k = 0; k < 16; k++) s = fmaf(W2[m * 16 + k], h[k], s);
        g[m] = s * dinv;
    }
    uint4 pk;
    pk.x = h2u(__floats2half2_rn(g[0], g[1]));
    pk.y = h2u(__floats2half2_rn(g[2], g[3]));
    pk.z = h2u(__floats2half2_rn(g[4], g[5]));
    pk.w = h2u(__floats2half2_rn(g[6], g[7]));
    reinterpret_cast<uint4*>(&d_g2[i * 8])[0] = pk;
    reinterpret_cast<uint4*>(&d_acc2[i * 8])[0] = pk;
}

// edge scatter layer 2: acc2[col] += g2[row]   (16B gather + one red.v4.f16x2)
__global__ void __launch_bounds__(256) k_edge2(const void* __restrict__ ei, int E) {
    int e = blockIdx.x * blockDim.x + threadIdx.x;
    if (e >= E) return;
    int r, c;
    load_rc(ei, E, e, r, c);
    uint4 v = reinterpret_cast<const uint4*>(&d_g2[r * 8])[0];
    asm volatile("red.global.add.noftz.v4.f16x2 [%0], {%1,%2,%3,%4};"
                 :: "l"(&d_acc2[c * 8]), "r"(v.x), "r"(v.y), "r"(v.z), "r"(v.w)
                 : "memory");
}

// node epilogue: h2 = tanh(dinv*acc2 + b2); z = h2 . W3; pool z and count (2 atomics)
__global__ void k_node2(const void* __restrict__ batch,
                        const float* __restrict__ b2,
                        const float* __restrict__ W3) {
    int i = blockIdx.x * blockDim.x + threadIdx.x;
    if (i >= NN) return;
    float dinv = d_dinv[i];
    int b = d_is64 ? (int)((const long long*)batch)[i] : ((const int*)batch)[i];
    uint4 av = reinterpret_cast<const uint4*>(&d_acc2[i * 8])[0];
    float2 a0 = __half22float2(u2h(av.x));
    float2 a1 = __half22float2(u2h(av.y));
    float2 a2 = __half22float2(u2h(av.z));
    float2 a3 = __half22float2(u2h(av.w));
    float v[8] = {a0.x, a0.y, a1.x, a1.y, a2.x, a2.y, a3.x, a3.y};
    float z = 0.0f;
#pragma unroll
    for (int k = 0; k < 8; k++)
        z = fmaf(tanh_fast(fmaf(dinv, v[k], b2[k])), W3[k], z);
    atomicAdd(&d_zsum[b], z);
    atomicAdd(&d_cntf[b], 1.0f);
}

// final: out[g] = zsum/max(cnt,1) + b3
__global__ void k_final(const float* __restrict__ b3, float* __restrict__ out) {
    int g = blockIdx.x * blockDim.x + threadIdx.x;
    if (g >= GG) return;
    float c = fmaxf(d_cntf[g], 1.0f);
    out[g] = d_zsum[g] / c + b3[0];
}

extern "C" void kernel_launch(void* const* d_in, const int* in_sizes, int n_in,
                              void* d_out, int out_size) {
    const float* x     = (const float*)d_in[0];
    const void*  ei    = d_in[1];
    const void*  batch = d_in[2];
    const float* W_emb = (const float*)d_in[3];
    const float* b_emb = (const float*)d_in[4];
    const float* W1    = (const float*)d_in[5];
    const float* b1    = (const float*)d_in[6];
    const float* W2    = (const float*)d_in[7];
    const float* b2    = (const float*)d_in[8];
    const float* W3    = (const float*)d_in[9];
    const float* b3    = (const float*)d_in[10];
    float* out = (float*)d_out;

    int E = in_sizes[1] / 2;
    if (E > EE) E = EE;

    int nb = (NN + 255) / 256;
    int eb = (E + 255) / 256;

    k_init<<<nb, 256>>>((const int*)ei);
    k_prep<<<eb, 256>>>(ei, E);
    k_node0<<<nb, 256>>>(x);
    k_edge1<<<eb, 256>>>(ei, E);
    k_node1<<<nb, 256>>>(W_emb, b_emb, W1, b1, W2);
    k_edge2<<<eb, 256>>>(ei, E);
    k_node2<<<nb, 256>>>(batch, b2, W3);
    k_final<<<(GG + 255) / 256, 256>>>(b3, out);
}